// round 6
// baseline (speedup 1.0000x reference)
#include <cuda_runtime.h>
#include <math.h>

#define NB   128   // N dialogues
#define LSEQ 64    // L
#define EDIM 300
#define HDIM 300
#define KF   40    // KEFF
#define NQ   127   // N-1
#define NHOPS 3
#define NCLS 6

// ---------------- scratch (device globals; no allocation) ----------------
__device__ float g_gi_utt[(size_t)LSEQ * NB * 1800];     // [t*128+b, 1800]
__device__ float g_h_utt[2][2 * NB * HDIM];
__device__ float g_maxpool[NB * 2 * HDIM];
__device__ float g_u[NB * HDIM];
__device__ float g_inp0[KF * NQ * HDIM];                 // ctx_t time-major
__device__ float g_gi_ctx[(size_t)KF * NQ * 1800];
__device__ float g_seq_ctx[2 * KF * NQ * HDIM];          // [dir, t, i, j]
__device__ float g_h_ctx[2][2 * NQ * HDIM];
__device__ float g_mem[KF * NQ * HDIM];                  // time-major [k,i,j]
__device__ float g_xr[(size_t)KF * NQ * 1800];
__device__ float g_xw[(size_t)KF * NQ * 1800];
__device__ float g_gates[KF * NQ];
__device__ float g_query[NQ * HDIM];
__device__ float g_h_att[2][2 * NQ * HDIM];

__device__ __forceinline__ float sigf(float x) { return 1.f / (1.f + expf(-x)); }

// ---------------- generic GEMM: C = A(MxK) @ W(NxK)^T + bias, opt gather/tanh ----
#define GTM 64
#define GTN 64
#define GTK 16

template<int GATHER, int EPI>
__global__ __launch_bounds__(256)
void gemm_kernel(const float* __restrict__ A, int lda,
                 const float* __restrict__ W,
                 const float* __restrict__ bias,
                 float* __restrict__ C, int ldc,
                 int M, int N, int K,
                 const float* __restrict__ emb,
                 const int* __restrict__ ids)
{
    __shared__ float As[GTK][GTM + 1];
    __shared__ float Bs[GTK][GTN + 1];
    __shared__ int   rowid[GTM];
    const int tid = threadIdx.x;
    const int m0 = blockIdx.y * GTM;
    const int n0 = blockIdx.x * GTN;

    if (GATHER) {
        if (tid < GTM) {
            int m = m0 + tid;
            int t = m >> 7, b = m & 127;          // m = t*128 + b
            rowid[tid] = (m < M) ? ids[b * LSEQ + t] : 0;
        }
        __syncthreads();
    }

    float acc[4][4] = {};
    const int mt = tid >> 4;   // 0..15
    const int nt = tid & 15;   // 0..15

    for (int k0 = 0; k0 < K; k0 += GTK) {
#pragma unroll
        for (int i = 0; i < 4; i++) {
            int idx = tid + i * 256;
            int mm = idx >> 4, kk = idx & 15;
            int m = m0 + mm, k = k0 + kk;
            float v = 0.f;
            if (m < M && k < K) {
                if (GATHER) v = emb[(long)rowid[mm] * K + k];
                else        v = A[(long)m * lda + k];
            }
            As[kk][mm] = v;
        }
#pragma unroll
        for (int i = 0; i < 4; i++) {
            int idx = tid + i * 256;
            int nn = idx >> 4, kk = idx & 15;
            int n = n0 + nn, k = k0 + kk;
            Bs[kk][nn] = (n < N && k < K) ? W[(long)n * K + k] : 0.f;
        }
        __syncthreads();
#pragma unroll
        for (int kk = 0; kk < GTK; kk++) {
            float a[4], b[4];
#pragma unroll
            for (int i = 0; i < 4; i++) a[i] = As[kk][mt * 4 + i];
#pragma unroll
            for (int j = 0; j < 4; j++) b[j] = Bs[kk][nt * 4 + j];
#pragma unroll
            for (int i = 0; i < 4; i++)
#pragma unroll
                for (int j = 0; j < 4; j++)
                    acc[i][j] += a[i] * b[j];
        }
        __syncthreads();
    }
#pragma unroll
    for (int i = 0; i < 4; i++) {
        int m = m0 + mt * 4 + i;
        if (m >= M) continue;
#pragma unroll
        for (int j = 0; j < 4; j++) {
            int n = n0 + nt * 4 + j;
            if (n >= N) continue;
            float v = acc[i][j] + bias[n];
            if (EPI == 1) v = tanhf(v);
            C[(long)m * ldc + n] = v;
        }
    }
}

// ---------------- fused GRU step (both dirs in one launch) ----------------
// MODE 0: utt (mask + reversed gi index + running max-pool)
// MODE 1: ctx (full lengths, store per-step output sequence)
#define SB 32
#define SJ 16
#define SK 16

template<int MODE>
__global__ __launch_bounds__(128)
void gru_step_kernel(const float* __restrict__ h_prev,
                     float* __restrict__ h_next,
                     const float* __restrict__ gi,      // [T*B, 1800]
                     const float* __restrict__ Whh,     // [2,900,300]
                     const float* __restrict__ bhh,     // [2,900]
                     const int*   __restrict__ seq_lens,
                     float* __restrict__ maxpool,       // [B, 600]
                     float* __restrict__ seqout,        // [2,T,B,300]
                     int t, int B, int T)
{
    __shared__ float As[SK][SB + 1];
    __shared__ float Bs[SK][3 * SJ + 1];
    const int tid = threadIdx.x;           // 128
    const int j0  = blockIdx.x * SJ;
    const int b0  = blockIdx.y * SB;
    const int dir = blockIdx.z;
    const float* hsrc = h_prev + (long)dir * B * HDIM;

    float acc[4][3] = {};
    const int mt = tid >> 4;   // 0..7
    const int jj = tid & 15;

    for (int k0 = 0; k0 < HDIM; k0 += SK) {
#pragma unroll
        for (int i = 0; i < 4; i++) {
            int idx = tid + i * 128;
            int mm = idx >> 4, kk = idx & 15;
            int b = b0 + mm, k = k0 + kk;
            As[kk][mm] = (b < B && k < HDIM) ? hsrc[(long)b * HDIM + k] : 0.f;
        }
#pragma unroll
        for (int i = 0; i < 6; i++) {
            int idx = tid + i * 128;
            int nn = idx >> 4, kk = idx & 15;        // nn 0..47
            int g = nn >> 4, jr = nn & 15;
            int j = j0 + jr, k = k0 + kk;
            Bs[kk][nn] = (j < HDIM && k < HDIM)
                       ? Whh[((long)dir * 900 + g * 300 + j) * 300 + k] : 0.f;
        }
        __syncthreads();
#pragma unroll
        for (int kk = 0; kk < SK; kk++) {
            float a[4];
#pragma unroll
            for (int i = 0; i < 4; i++) a[i] = As[kk][mt * 4 + i];
            float br = Bs[kk][jj], bz = Bs[kk][16 + jj], bn = Bs[kk][32 + jj];
#pragma unroll
            for (int i = 0; i < 4; i++) {
                acc[i][0] += a[i] * br;
                acc[i][1] += a[i] * bz;
                acc[i][2] += a[i] * bn;
            }
        }
        __syncthreads();
    }

    const int j = j0 + jj;
    if (j >= HDIM) return;
    const float bhr = bhh[dir * 900 + j];
    const float bhz = bhh[dir * 900 + 300 + j];
    const float bhn = bhh[dir * 900 + 600 + j];
#pragma unroll
    for (int i = 0; i < 4; i++) {
        int b = b0 + mt * 4 + i;
        if (b >= B) continue;
        float ghr = acc[i][0] + bhr, ghz = acc[i][1] + bhz, ghn = acc[i][2] + bhn;
        int trow; bool mask = true;
        if (MODE == 0) {
            int len = seq_lens[b];
            mask = (t < len);
            trow = (dir == 0) ? t : max(len - 1 - t, 0);
        } else {
            trow = (dir == 0) ? t : (T - 1 - t);
        }
        const float* gr = gi + ((long)trow * B + b) * 1800 + dir * 900 + j;
        float r = sigf(gr[0] + ghr);
        float z = sigf(gr[300] + ghz);
        float n = tanhf(gr[600] + r * ghn);
        float hold = hsrc[(long)b * HDIM + j];
        float hnew = (1.f - z) * n + z * hold;
        if (MODE == 0) {
            float hf = mask ? hnew : hold;
            h_next[(long)dir * B * HDIM + b * HDIM + j] = hf;
            float mp = mask ? hnew : 0.f;
            float* mpp = &maxpool[b * (2 * HDIM) + dir * HDIM + j];
            *mpp = fmaxf(*mpp, mp);
        } else {
            h_next[(long)dir * B * HDIM + b * HDIM + j] = hnew;
            seqout[((long)dir * T + t) * B * HDIM + b * HDIM + j] = hnew;
        }
    }
}

// ---------------- fused attention-GRU step (both dirs in one launch) -------
__global__ __launch_bounds__(128)
void att_step_kernel(const float* __restrict__ h_prev,
                     float* __restrict__ h_next,
                     const float* __restrict__ xr,   // [40*127, 1800]
                     const float* __restrict__ xw,
                     const float* __restrict__ Ur,   // [3,2,300,300]
                     const float* __restrict__ Uw,
                     const float* __restrict__ bur,  // [3,2,300]
                     const float* __restrict__ bu,
                     const float* __restrict__ gates, // [40*127]
                     int t, int hop)
{
    __shared__ float As[SK][SB + 1];
    __shared__ float Bs[SK][2 * SJ + 1];
    const int tid = threadIdx.x;         // 128
    const int j0  = blockIdx.x * SJ;
    const int b0  = blockIdx.y * SB;
    const int dir = blockIdx.z;
    const int wd  = hop * 2 + dir;
    const float* hsrc = h_prev + (long)dir * NQ * HDIM;

    float acc[4][2] = {};
    const int mt = tid >> 4;
    const int jj = tid & 15;

    for (int k0 = 0; k0 < HDIM; k0 += SK) {
#pragma unroll
        for (int i = 0; i < 4; i++) {
            int idx = tid + i * 128;
            int mm = idx >> 4, kk = idx & 15;
            int b = b0 + mm, k = k0 + kk;
            As[kk][mm] = (b < NQ && k < HDIM) ? hsrc[(long)b * HDIM + k] : 0.f;
        }
#pragma unroll
        for (int i = 0; i < 4; i++) {
            int idx = tid + i * 128;
            int nn = idx >> 4, kk = idx & 15;        // nn 0..31
            int g = nn >> 4, jr = nn & 15;
            int j = j0 + jr, k = k0 + kk;
            const float* Wsrc = (g == 0) ? Ur : Uw;
            Bs[kk][nn] = (j < HDIM && k < HDIM)
                       ? Wsrc[((long)wd * 300 + j) * 300 + k] : 0.f;
        }
        __syncthreads();
#pragma unroll
        for (int kk = 0; kk < SK; kk++) {
            float a[4];
#pragma unroll
            for (int i = 0; i < 4; i++) a[i] = As[kk][mt * 4 + i];
            float b0v = Bs[kk][jj], b1v = Bs[kk][16 + jj];
#pragma unroll
            for (int i = 0; i < 4; i++) {
                acc[i][0] += a[i] * b0v;
                acc[i][1] += a[i] * b1v;
            }
        }
        __syncthreads();
    }

    const int j = j0 + jj;
    if (j >= HDIM) return;
    const int tt = (dir == 0) ? t : (KF - 1 - t);
    const float burv = bur[wd * 300 + j];
    const float buv  = bu[wd * 300 + j];
#pragma unroll
    for (int i = 0; i < 4; i++) {
        int b = b0 + mt * 4 + i;
        if (b >= NQ) continue;
        long xrow = ((long)tt * NQ + b) * 1800 + wd * 300 + j;
        float r  = sigf(xr[xrow] + acc[i][0] + burv);
        float ht = tanhf(xw[xrow] + r * (acc[i][1] + buv));
        float g  = gates[tt * NQ + b];
        float hold = hsrc[(long)b * HDIM + j];
        h_next[(long)dir * NQ * HDIM + b * HDIM + j] = g * ht + (1.f - g) * hold;
    }
}

// ---------------- small kernels ----------------
__global__ void fillk(float* p, float v, int n) {
    int i = blockIdx.x * blockDim.x + threadIdx.x;
    if (i < n) p[i] = v;
}

__global__ void build_inp0(const float* __restrict__ u, float* __restrict__ inp0) {
    int idx = blockIdx.x * blockDim.x + threadIdx.x;
    if (idx >= KF * NQ * HDIM) return;
    int j = idx % HDIM;
    int r = idx / HDIM;
    int i = r % NQ;
    int k = r / NQ;
    int src = (i + 1) - KF + k;
    inp0[idx] = (src >= 0) ? u[src * HDIM + j] : 0.f;
}

__global__ void membank_kernel(const float* __restrict__ inp0,
                               const float* __restrict__ seq,
                               float* __restrict__ mem) {
    int idx = blockIdx.x * blockDim.x + threadIdx.x;
    if (idx >= KF * NQ * HDIM) return;
    int j = idx % HDIM;
    int r = idx / HDIM;
    int i = r % NQ;
    int k = r / NQ;
    float f = seq[((long)k) * NQ * HDIM + i * HDIM + j];
    float b = seq[((long)KF + (KF - 1 - k)) * NQ * HDIM + i * HDIM + j];
    mem[idx] = inp0[idx] + f + b;
}

__global__ void score_kernel(const float* __restrict__ query,
                             const float* __restrict__ mem,
                             float* __restrict__ gates) {
    int b = blockIdx.x;                 // 0..126
    int tid = threadIdx.x;              // 128
    int lane = tid & 31, w = tid >> 5;
    __shared__ float q[HDIM];
    __shared__ float logit[KF];
    for (int i = tid; i < HDIM; i += 128) q[i] = query[b * HDIM + i];
    __syncthreads();
    for (int k = w; k < KF; k += 4) {
        const float* mrow = mem + ((long)k * NQ + b) * HDIM;
        float s = 0.f;
        for (int i = lane; i < HDIM; i += 32) s += q[i] * mrow[i];
        for (int o = 16; o > 0; o >>= 1) s += __shfl_xor_sync(0xffffffffu, s, o);
        if (lane == 0) logit[k] = (k >= KF - 1 - b) ? s : -1e10f;
    }
    __syncthreads();
    if (w == 0) {
        float m = -INFINITY;
        for (int k = lane; k < KF; k += 32) m = fmaxf(m, logit[k]);
        for (int o = 16; o > 0; o >>= 1) m = fmaxf(m, __shfl_xor_sync(0xffffffffu, m, o));
        float ssum = 0.f;
        for (int k = lane; k < KF; k += 32) { float e = expf(logit[k] - m); logit[k] = e; ssum += e; }
        for (int o = 16; o > 0; o >>= 1) ssum += __shfl_xor_sync(0xffffffffu, ssum, o);
        for (int k = lane; k < KF; k += 32) gates[k * NQ + b] = logit[k] / ssum;
    }
}

__global__ void add2_kernel(float* __restrict__ q,
                            const float* __restrict__ hf,
                            const float* __restrict__ hb, int n) {
    int i = blockIdx.x * blockDim.x + threadIdx.x;
    if (i < n) q[i] += hf[i] + hb[i];
}

__global__ void cls_kernel(const float* __restrict__ u,
                           const float* __restrict__ query,
                           const float* __restrict__ cls_w,
                           const float* __restrict__ cls_b,
                           float* __restrict__ out) {
    int row = blockIdx.x;               // 0..127
    int w = threadIdx.x >> 5, lane = threadIdx.x & 31;   // 192 threads = 6 warps
    const float* s = (row == 0) ? u : (query + (row - 1) * HDIM);
    float acc = 0.f;
    for (int i = lane; i < HDIM; i += 32) acc += s[i] * cls_w[w * HDIM + i];
    for (int o = 16; o > 0; o >>= 1) acc += __shfl_xor_sync(0xffffffffu, acc, o);
    if (lane == 0) out[row * NCLS + w] = acc + cls_b[w];
}

// ---------------- host orchestration ----------------
extern "C" void kernel_launch(void* const* d_in, const int* in_sizes, int n_in,
                              void* d_out, int out_size) {
    const int*   ids      = (const int*)d_in[0];
    const int*   seq_lens = (const int*)d_in[1];
    const float* emb      = (const float*)d_in[2];
    const float* utt_Wih  = (const float*)d_in[3];
    const float* utt_Whh  = (const float*)d_in[4];
    const float* utt_bih  = (const float*)d_in[5];
    const float* utt_bhh  = (const float*)d_in[6];
    const float* lin_w    = (const float*)d_in[7];
    const float* lin_b    = (const float*)d_in[8];
    const float* ctx_Wih  = (const float*)d_in[9];
    const float* ctx_Whh  = (const float*)d_in[10];
    const float* ctx_bih  = (const float*)d_in[11];
    const float* ctx_bhh  = (const float*)d_in[12];
    const float* aWr_w    = (const float*)d_in[13];
    const float* aWr_b    = (const float*)d_in[14];
    const float* aUr_w    = (const float*)d_in[15];
    const float* aUr_b    = (const float*)d_in[16];
    const float* aW_w     = (const float*)d_in[17];
    const float* aW_b     = (const float*)d_in[18];
    const float* aU_w     = (const float*)d_in[19];
    const float* aU_b     = (const float*)d_in[20];
    const float* cls_w    = (const float*)d_in[21];
    const float* cls_b    = (const float*)d_in[22];
    float* out = (float*)d_out;

    float *gi_utt, *h_utt, *maxpool, *u, *inp0, *gi_ctx, *seq_ctx, *h_ctx;
    float *mem, *xr, *xw, *gates, *query, *h_att;
    cudaGetSymbolAddress((void**)&gi_utt,  g_gi_utt);
    cudaGetSymbolAddress((void**)&h_utt,   g_h_utt);
    cudaGetSymbolAddress((void**)&maxpool, g_maxpool);
    cudaGetSymbolAddress((void**)&u,       g_u);
    cudaGetSymbolAddress((void**)&inp0,    g_inp0);
    cudaGetSymbolAddress((void**)&gi_ctx,  g_gi_ctx);
    cudaGetSymbolAddress((void**)&seq_ctx, g_seq_ctx);
    cudaGetSymbolAddress((void**)&h_ctx,   g_h_ctx);
    cudaGetSymbolAddress((void**)&mem,     g_mem);
    cudaGetSymbolAddress((void**)&xr,      g_xr);
    cudaGetSymbolAddress((void**)&xw,      g_xw);
    cudaGetSymbolAddress((void**)&gates,   g_gates);
    cudaGetSymbolAddress((void**)&query,   g_query);
    cudaGetSymbolAddress((void**)&h_att,   g_h_att);

    float* hU[2] = { h_utt, h_utt + 2 * NB * HDIM };
    float* hC[2] = { h_ctx, h_ctx + 2 * NQ * HDIM };
    float* hA[2] = { h_att, h_att + 2 * NQ * HDIM };

    cudaStream_t s = 0;

    // ---- init ----
    fillk<<<(NB * 2 * HDIM + 255) / 256, 256, 0, s>>>(maxpool, -1e30f, NB * 2 * HDIM);
    fillk<<<(2 * NB * HDIM + 255) / 256, 256, 0, s>>>(hU[0], 0.f, 2 * NB * HDIM);

    // ---- utterance GRU input projection (gathered emb) ----
    {
        dim3 g((1800 + GTN - 1) / GTN, (LSEQ * NB + GTM - 1) / GTM);
        gemm_kernel<1, 0><<<g, 256, 0, s>>>(nullptr, 0, utt_Wih, utt_bih,
                                            gi_utt, 1800, LSEQ * NB, 1800, EDIM, emb, ids);
    }
    // ---- utterance GRU scan (64 steps, both dirs) ----
    {
        dim3 g((HDIM + SJ - 1) / SJ, (NB + SB - 1) / SB, 2);
        int cur = 0;
        for (int t = 0; t < LSEQ; t++) {
            gru_step_kernel<0><<<g, 128, 0, s>>>(hU[cur], hU[cur ^ 1], gi_utt,
                                                 utt_Whh, utt_bhh, seq_lens,
                                                 maxpool, nullptr, t, NB, LSEQ);
            cur ^= 1;
        }
    }
    // ---- u = tanh(maxpool @ lin_w^T + lin_b) ----
    {
        dim3 g((HDIM + GTN - 1) / GTN, (NB + GTM - 1) / GTM);
        gemm_kernel<0, 1><<<g, 256, 0, s>>>(maxpool, 2 * HDIM, lin_w, lin_b,
                                            u, HDIM, NB, HDIM, 2 * HDIM, nullptr, nullptr);
    }
    // ---- context windows + ctx GRU ----
    build_inp0<<<(KF * NQ * HDIM + 255) / 256, 256, 0, s>>>(u, inp0);
    fillk<<<(2 * NQ * HDIM + 255) / 256, 256, 0, s>>>(hC[0], 0.f, 2 * NQ * HDIM);
    {
        dim3 g((1800 + GTN - 1) / GTN, (KF * NQ + GTM - 1) / GTM);
        gemm_kernel<0, 0><<<g, 256, 0, s>>>(inp0, HDIM, ctx_Wih, ctx_bih,
                                            gi_ctx, 1800, KF * NQ, 1800, HDIM, nullptr, nullptr);
    }
    {
        dim3 g((HDIM + SJ - 1) / SJ, (NQ + SB - 1) / SB, 2);
        int cur = 0;
        for (int t = 0; t < KF; t++) {
            gru_step_kernel<1><<<g, 128, 0, s>>>(hC[cur], hC[cur ^ 1], gi_ctx,
                                                 ctx_Whh, ctx_bhh, nullptr,
                                                 nullptr, seq_ctx, t, NQ, KF);
            cur ^= 1;
        }
    }
    membank_kernel<<<(KF * NQ * HDIM + 255) / 256, 256, 0, s>>>(inp0, seq_ctx, mem);

    // ---- attention x-projections (hop-invariant, all hops/dirs in one GEMM each) ----
    {
        dim3 g((1800 + GTN - 1) / GTN, (KF * NQ + GTM - 1) / GTM);
        gemm_kernel<0, 0><<<g, 256, 0, s>>>(mem, HDIM, aWr_w, aWr_b,
                                            xr, 1800, KF * NQ, 1800, HDIM, nullptr, nullptr);
        gemm_kernel<0, 0><<<g, 256, 0, s>>>(mem, HDIM, aW_w, aW_b,
                                            xw, 1800, KF * NQ, 1800, HDIM, nullptr, nullptr);
    }

    // ---- query init + hops ----
    cudaMemcpyAsync(query, u + HDIM, NQ * HDIM * sizeof(float),
                    cudaMemcpyDeviceToDevice, s);
    dim3 ga((HDIM + SJ - 1) / SJ, (NQ + SB - 1) / SB, 2);
    for (int hop = 0; hop < NHOPS; hop++) {
        score_kernel<<<NQ, 128, 0, s>>>(query, mem, gates);
        fillk<<<(2 * NQ * HDIM + 255) / 256, 256, 0, s>>>(hA[0], 0.f, 2 * NQ * HDIM);
        int cur = 0;
        for (int t = 0; t < KF; t++) {
            att_step_kernel<<<ga, 128, 0, s>>>(hA[cur], hA[cur ^ 1], xr, xw,
                                               aUr_w, aU_w, aUr_b, aU_b,
                                               gates, t, hop);
            cur ^= 1;
        }
        add2_kernel<<<(NQ * HDIM + 255) / 256, 256, 0, s>>>(
            query, hA[cur], hA[cur] + NQ * HDIM, NQ * HDIM);
    }

    // ---- classifier ----
    cls_kernel<<<NB, 192, 0, s>>>(u, query, cls_w, cls_b, out);
}